// round 9
// baseline (speedup 1.0000x reference)
#include <cuda_runtime.h>
#include <cuda_bf16.h>

#define V_SZ 8
#define J_SZ 64
#define NTHREADS 256          // 8 warps; warp w owns view w
#define BPB 8                 // batch elements per block
#define T09 219.711923f       // 400^0.9
#define THRESH 400.0f
#define MAX_BLOCKS 8192

// Scratch (allocation-free rule: __device__ globals)
__device__ float g_part[MAX_BLOCKS];
__device__ unsigned g_ctr = 0;

// Per-buffer layout (576 floats):
// [0,192)=gt kps AoS, [192,384)=pred kps AoS, [384,456)=R, [456,480)=t, [480,576)=cam
__device__ __forceinline__ void stage_ldg(
    int b, int tid,
    const float* __restrict__ kgt, const float* __restrict__ kpr,
    const float* __restrict__ gR,  const float* __restrict__ gt,
    const float* __restrict__ cam, float4& v4)
{
    if (tid < 48)       v4 = reinterpret_cast<const float4*>(kgt + (size_t)b * 192)[tid];
    else if (tid < 96)  v4 = reinterpret_cast<const float4*>(kpr + (size_t)b * 192)[tid - 48];
    else if (tid < 114) v4 = reinterpret_cast<const float4*>(gR  + (size_t)b * 72 )[tid - 96];
    else if (tid < 120) v4 = reinterpret_cast<const float4*>(gt  + (size_t)b * 24 )[tid - 114];
    else                v4 = reinterpret_cast<const float4*>(cam + (size_t)b * 96 )[tid - 120];
}

__device__ __forceinline__ void fuse_mats(
    int tid, const float* __restrict__ s, const float* __restrict__ s_K,
    float* __restrict__ M, float* __restrict__ Mc)
{
    // M = K@[R|t] (12/view), Mc = K@cam (12/view): 192 entries, 3 FMA each
    if (tid < 192) {
        const int v = tid / 24;
        const int r = tid % 24;
        const float* Kv = s_K + v * 9;
        if (r < 12) {
            const int i = r >> 2, c = r & 3;
            float e0, e1, e2;
            if (c < 3) { const float* Rv = s + 384 + v * 9; e0 = Rv[c]; e1 = Rv[3 + c]; e2 = Rv[6 + c]; }
            else       { const float* tv = s + 456 + v * 3; e0 = tv[0]; e1 = tv[1]; e2 = tv[2]; }
            M[v * 12 + r] = Kv[i * 3 + 0] * e0 + Kv[i * 3 + 1] * e1 + Kv[i * 3 + 2] * e2;
        } else {
            const int r2 = r - 12;
            const int i = r2 >> 2, c = r2 & 3;
            const float* Cv = s + 480 + v * 12;
            Mc[v * 12 + r2] = Kv[i * 3 + 0] * Cv[c] + Kv[i * 3 + 1] * Cv[4 + c] + Kv[i * 3 + 2] * Cv[8 + c];
        }
    }
}

__global__ void __launch_bounds__(NTHREADS) pl_kernel(
    const float* __restrict__ kgt,   // [B,J,3]
    const float* __restrict__ kpr,   // [B,J,3]
    const float* __restrict__ gR,    // [B,V,3,3]
    const float* __restrict__ gt,    // [B,V,3]
    const float* __restrict__ Km,    // [V,3,3]
    const float* __restrict__ cam,   // [B,V,3,4]
    float* __restrict__ out, int B, int nblocks)
{
    __shared__ __align__(16) float buf[2][576];
    __shared__ float s_M[2][96];
    __shared__ float s_Mc[2][96];
    __shared__ float s_K[72];
    __shared__ float s_wsum[NTHREADS / 32];
    __shared__ double s_d[NTHREADS / 32];
    __shared__ bool s_last;

    const int tid  = threadIdx.x;
    const int w    = tid >> 5;
    const int lane = tid & 31;
    const int b0   = blockIdx.x * BPB;

    if (tid < 72) s_K[tid] = Km[tid];

    // ---- Prologue: stage + fuse batch b0
    float4 v4;
    if (tid < 144 && b0 < B) {
        stage_ldg(b0, tid, kgt, kpr, gR, gt, cam, v4);
        reinterpret_cast<float4*>(buf[0])[tid] = v4;
    }
    __syncthreads();                       // buf[0] + s_K visible
    if (b0 < B) fuse_mats(tid, buf[0], s_K, s_M[0], s_Mc[0]);
    __syncthreads();                       // fused matrices visible

    float acc = 0.0f;

    #pragma unroll
    for (int bb = 0; bb < BPB; bb++) {
        const int cur = bb & 1, nxt = cur ^ 1;
        const int b = b0 + bb;
        const bool pf = (bb + 1 < BPB) && (b0 + bb + 1 < B) && (tid < 144);

        // Kick off prefetch of next batch (LDG latency hidden by compute below)
        if (pf) stage_ldg(b + 1, tid, kgt, kpr, gR, gt, cam, v4);

        if (b < B) {
            const float* s = buf[cur];
            float m[12], mc[12];
            #pragma unroll
            for (int i = 0; i < 12; i++) { m[i] = s_M[cur][w * 12 + i]; mc[i] = s_Mc[cur][w * 12 + i]; }

            #pragma unroll
            for (int jj = 0; jj < 2; jj++) {
                const int j = lane + jj * 32;
                const float X0 = s[j * 3 + 0], X1 = s[j * 3 + 1], X2 = s[j * 3 + 2];
                const float x0 = m[3]  + m[0] * X0 + m[1] * X1 + m[2]  * X2;
                const float x1 = m[7]  + m[4] * X0 + m[5] * X1 + m[6]  * X2;
                const float x2 = m[11] + m[8] * X0 + m[9] * X1 + m[10] * X2;

                const float P0 = s[192 + j * 3 + 0], P1 = s[192 + j * 3 + 1], P2 = s[192 + j * 3 + 2];
                const float y0 = mc[3]  + mc[0] * P0 + mc[1] * P1 + mc[2]  * P2;
                const float y1 = mc[7]  + mc[4] * P0 + mc[5] * P1 + mc[6]  * P2;
                const float y2 = mc[11] + mc[8] * P0 + mc[9] * P1 + mc[10] * P2;

                // gx-px = (x0*y2 - y0*x2) / (x2*y2): one rcp serves both components
                const float r  = __fdividef(1.0f, x2 * y2);
                float dx = (x0 * y2 - y0 * x2) * r;
                float dy = (x1 * y2 - y1 * x2) * r;
                dx *= dx; dy *= dy;
                acc += (dx > THRESH) ? (__powf(dx, 0.1f) * T09) : dx;
                acc += (dy > THRESH) ? (__powf(dy, 0.1f) * T09) : dy;
            }
        }

        // Commit prefetched data to the alternate buffer
        if (pf) reinterpret_cast<float4*>(buf[nxt])[tid] = v4;
        __syncthreads();                   // buf[nxt] complete; buf[cur] consumed
        if (bb + 1 < BPB && b0 + bb + 1 < B)
            fuse_mats(tid, buf[nxt], s_K, s_M[nxt], s_Mc[nxt]);
        __syncthreads();                   // fused matrices for next iter visible
    }

    // ---- Block reduction: one float per block
    #pragma unroll
    for (int o = 16; o > 0; o >>= 1)
        acc += __shfl_down_sync(0xFFFFFFFFu, acc, o);
    if (lane == 0) s_wsum[w] = acc;
    __syncthreads();
    if (tid < (NTHREADS / 32)) {
        float t = s_wsum[tid];
        #pragma unroll
        for (int o = (NTHREADS / 64); o > 0; o >>= 1)
            t += __shfl_down_sync(0xFFu, t, o);
        if (tid == 0) g_part[blockIdx.x] = t;
    }
    __threadfence();
    __syncthreads();

    // ---- Last block performs the final reduction (fixed order: deterministic)
    if (tid == 0) {
        unsigned c = atomicAdd(&g_ctr, 1);
        s_last = (c == gridDim.x - 1);
    }
    __syncthreads();
    if (s_last) {
        double dsum = 0.0;
        for (int i = tid; i < nblocks; i += NTHREADS)
            dsum += (double)__ldcg(&g_part[i]);
        #pragma unroll
        for (int o = 16; o > 0; o >>= 1)
            dsum += __shfl_down_sync(0xFFFFFFFFu, dsum, o);
        if (lane == 0) s_d[w] = dsum;
        __syncthreads();
        if (tid < (NTHREADS / 32)) {
            double t2 = s_d[tid];
            #pragma unroll
            for (int o = (NTHREADS / 64); o > 0; o >>= 1)
                t2 += __shfl_down_sync(0xFFu, t2, o);
            if (tid == 0) {
                *out = (float)(t2 / (2.0 * (double)B));
                g_ctr = 0;   // reset for next graph replay
            }
        }
    }
}

extern "C" void kernel_launch(void* const* d_in, const int* in_sizes, int n_in,
                              void* d_out, int out_size) {
    const float* kgt = (const float*)d_in[0];   // [B,J,3]
    const float* kpr = (const float*)d_in[1];   // [B,J,3]
    const float* gR  = (const float*)d_in[2];   // [B,V,3,3]
    const float* gt  = (const float*)d_in[3];   // [B,V,3]
    const float* Km  = (const float*)d_in[4];   // [V,3,3]
    const float* cam = (const float*)d_in[5];   // [B,V,3,4]
    float* out = (float*)d_out;

    const int B = in_sizes[0] / (J_SZ * 3);
    const int nblocks = (B + BPB - 1) / BPB;    // 2048 for B=16384

    pl_kernel<<<nblocks, NTHREADS>>>(kgt, kpr, gR, gt, Km, cam, out, B, nblocks);
}

// round 10
// speedup vs baseline: 1.0069x; 1.0069x over previous
#include <cuda_runtime.h>
#include <cuda_bf16.h>

#define V_SZ 8
#define J_SZ 64
#define NTHREADS 256          // 8 warps; warp w owns view w
#define BPB 8                 // batch elements per block
#define T09 219.711923f       // 400^0.9
#define THRESH 400.0f
#define MAX_BLOCKS 8192

// Scratch (allocation-free rule: __device__ globals)
__device__ float g_part[MAX_BLOCKS];
__device__ unsigned g_ctr = 0;

// Per-buffer layout (576 floats):
// [0,192)=gt kps AoS, [192,384)=pred kps AoS, [384,456)=R, [456,480)=t, [480,576)=cam
__device__ __forceinline__ void stage_ldg(
    int b, int tid,
    const float* __restrict__ kgt, const float* __restrict__ kpr,
    const float* __restrict__ gR,  const float* __restrict__ gt,
    const float* __restrict__ cam, float4& v4)
{
    if (tid < 48)       v4 = reinterpret_cast<const float4*>(kgt + (size_t)b * 192)[tid];
    else if (tid < 96)  v4 = reinterpret_cast<const float4*>(kpr + (size_t)b * 192)[tid - 48];
    else if (tid < 114) v4 = reinterpret_cast<const float4*>(gR  + (size_t)b * 72 )[tid - 96];
    else if (tid < 120) v4 = reinterpret_cast<const float4*>(gt  + (size_t)b * 24 )[tid - 114];
    else                v4 = reinterpret_cast<const float4*>(cam + (size_t)b * 96 )[tid - 120];
}

__device__ __forceinline__ void fuse_mats(
    int tid, const float* __restrict__ s, const float* __restrict__ s_K,
    float* __restrict__ M, float* __restrict__ Mc)
{
    // M = K@[R|t] (12/view), Mc = K@cam (12/view): 192 entries, 3 FMA each
    if (tid < 192) {
        const int v = tid / 24;
        const int r = tid % 24;
        const float* Kv = s_K + v * 9;
        if (r < 12) {
            const int i = r >> 2, c = r & 3;
            float e0, e1, e2;
            if (c < 3) { const float* Rv = s + 384 + v * 9; e0 = Rv[c]; e1 = Rv[3 + c]; e2 = Rv[6 + c]; }
            else       { const float* tv = s + 456 + v * 3; e0 = tv[0]; e1 = tv[1]; e2 = tv[2]; }
            M[v * 12 + r] = Kv[i * 3 + 0] * e0 + Kv[i * 3 + 1] * e1 + Kv[i * 3 + 2] * e2;
        } else {
            const int r2 = r - 12;
            const int i = r2 >> 2, c = r2 & 3;
            const float* Cv = s + 480 + v * 12;
            Mc[v * 12 + r2] = Kv[i * 3 + 0] * Cv[c] + Kv[i * 3 + 1] * Cv[4 + c] + Kv[i * 3 + 2] * Cv[8 + c];
        }
    }
}

__global__ void __launch_bounds__(NTHREADS) pl_kernel(
    const float* __restrict__ kgt,   // [B,J,3]
    const float* __restrict__ kpr,   // [B,J,3]
    const float* __restrict__ gR,    // [B,V,3,3]
    const float* __restrict__ gt,    // [B,V,3]
    const float* __restrict__ Km,    // [V,3,3]
    const float* __restrict__ cam,   // [B,V,3,4]
    float* __restrict__ out, int B, int nblocks)
{
    __shared__ __align__(16) float buf[2][576];
    __shared__ float s_M[2][96];
    __shared__ float s_Mc[2][96];
    __shared__ float s_K[72];
    __shared__ float s_wsum[NTHREADS / 32];
    __shared__ double s_d[NTHREADS / 32];
    __shared__ bool s_last;

    const int tid  = threadIdx.x;
    const int w    = tid >> 5;
    const int lane = tid & 31;
    const int b0   = blockIdx.x * BPB;

    if (tid < 72) s_K[tid] = Km[tid];

    // ---- Prologue: stage + fuse batch b0
    float4 v4;
    if (tid < 144 && b0 < B) {
        stage_ldg(b0, tid, kgt, kpr, gR, gt, cam, v4);
        reinterpret_cast<float4*>(buf[0])[tid] = v4;
    }
    __syncthreads();                       // buf[0] + s_K visible
    if (b0 < B) fuse_mats(tid, buf[0], s_K, s_M[0], s_Mc[0]);
    __syncthreads();                       // fused matrices visible

    float acc = 0.0f;

    #pragma unroll
    for (int bb = 0; bb < BPB; bb++) {
        const int cur = bb & 1, nxt = cur ^ 1;
        const int b = b0 + bb;
        const bool pf = (bb + 1 < BPB) && (b0 + bb + 1 < B) && (tid < 144);

        // Kick off prefetch of next batch (LDG latency hidden by compute below)
        if (pf) stage_ldg(b + 1, tid, kgt, kpr, gR, gt, cam, v4);

        if (b < B) {
            const float* s = buf[cur];
            float m[12], mc[12];
            #pragma unroll
            for (int i = 0; i < 12; i++) { m[i] = s_M[cur][w * 12 + i]; mc[i] = s_Mc[cur][w * 12 + i]; }

            #pragma unroll
            for (int jj = 0; jj < 2; jj++) {
                const int j = lane + jj * 32;
                const float X0 = s[j * 3 + 0], X1 = s[j * 3 + 1], X2 = s[j * 3 + 2];
                const float x0 = m[3]  + m[0] * X0 + m[1] * X1 + m[2]  * X2;
                const float x1 = m[7]  + m[4] * X0 + m[5] * X1 + m[6]  * X2;
                const float x2 = m[11] + m[8] * X0 + m[9] * X1 + m[10] * X2;

                const float P0 = s[192 + j * 3 + 0], P1 = s[192 + j * 3 + 1], P2 = s[192 + j * 3 + 2];
                const float y0 = mc[3]  + mc[0] * P0 + mc[1] * P1 + mc[2]  * P2;
                const float y1 = mc[7]  + mc[4] * P0 + mc[5] * P1 + mc[6]  * P2;
                const float y2 = mc[11] + mc[8] * P0 + mc[9] * P1 + mc[10] * P2;

                // gx-px = (x0*y2 - y0*x2) / (x2*y2): one rcp serves both components
                const float r  = __fdividef(1.0f, x2 * y2);
                float dx = (x0 * y2 - y0 * x2) * r;
                float dy = (x1 * y2 - y1 * x2) * r;
                dx *= dx; dy *= dy;
                acc += (dx > THRESH) ? (__powf(dx, 0.1f) * T09) : dx;
                acc += (dy > THRESH) ? (__powf(dy, 0.1f) * T09) : dy;
            }
        }

        // Commit prefetched data to the alternate buffer
        if (pf) reinterpret_cast<float4*>(buf[nxt])[tid] = v4;
        __syncthreads();                   // buf[nxt] complete; buf[cur] consumed
        if (bb + 1 < BPB && b0 + bb + 1 < B)
            fuse_mats(tid, buf[nxt], s_K, s_M[nxt], s_Mc[nxt]);
        __syncthreads();                   // fused matrices for next iter visible
    }

    // ---- Block reduction: one float per block
    #pragma unroll
    for (int o = 16; o > 0; o >>= 1)
        acc += __shfl_down_sync(0xFFFFFFFFu, acc, o);
    if (lane == 0) s_wsum[w] = acc;
    __syncthreads();
    if (tid < (NTHREADS / 32)) {
        float t = s_wsum[tid];
        #pragma unroll
        for (int o = (NTHREADS / 64); o > 0; o >>= 1)
            t += __shfl_down_sync(0xFFu, t, o);
        if (tid == 0) g_part[blockIdx.x] = t;
    }
    __threadfence();
    __syncthreads();

    // ---- Last block performs the final reduction (fixed order: deterministic)
    if (tid == 0) {
        unsigned c = atomicAdd(&g_ctr, 1);
        s_last = (c == gridDim.x - 1);
    }
    __syncthreads();
    if (s_last) {
        double dsum = 0.0;
        for (int i = tid; i < nblocks; i += NTHREADS)
            dsum += (double)__ldcg(&g_part[i]);
        #pragma unroll
        for (int o = 16; o > 0; o >>= 1)
            dsum += __shfl_down_sync(0xFFFFFFFFu, dsum, o);
        if (lane == 0) s_d[w] = dsum;
        __syncthreads();
        if (tid < (NTHREADS / 32)) {
            double t2 = s_d[tid];
            #pragma unroll
            for (int o = (NTHREADS / 64); o > 0; o >>= 1)
                t2 += __shfl_down_sync(0xFFu, t2, o);
            if (tid == 0) {
                *out = (float)(t2 / (2.0 * (double)B));
                g_ctr = 0;   // reset for next graph replay
            }
        }
    }
}

extern "C" void kernel_launch(void* const* d_in, const int* in_sizes, int n_in,
                              void* d_out, int out_size) {
    const float* kgt = (const float*)d_in[0];   // [B,J,3]
    const float* kpr = (const float*)d_in[1];   // [B,J,3]
    const float* gR  = (const float*)d_in[2];   // [B,V,3,3]
    const float* gt  = (const float*)d_in[3];   // [B,V,3]
    const float* Km  = (const float*)d_in[4];   // [V,3,3]
    const float* cam = (const float*)d_in[5];   // [B,V,3,4]
    float* out = (float*)d_out;

    const int B = in_sizes[0] / (J_SZ * 3);
    const int nblocks = (B + BPB - 1) / BPB;    // 2048 for B=16384

    pl_kernel<<<nblocks, NTHREADS>>>(kgt, kpr, gR, gt, Km, cam, out, B, nblocks);
}